// round 12
// baseline (speedup 1.0000x reference)
#include <cuda_runtime.h>

// SidNetLayer: N=50000, E=600000 per signed adjacency, D=128, K=10, C=0.15.
//   new_P = Ap*P + Am*M + 0.15*X
//   new_M = Am*P + Ap*M
// Merged signed CSR (sign in bit31), one warp per row (R7 structure).
// R12: gathers via cp.async.cg (LDGSTS, L1-BYPASS, L2->smem) into a per-warp
// 8-deep smem ring. MLP lives in the async-group scoreboard + smem, not in
// registers, so ptxas cannot re-serialize it (R8-R11 showed it always does
// for register-resident batching).

#define NMAX  50000
#define EMAX  600000
#define DD    128
#define DV    32          // D/4 float4 per row
#define KITER 10
#define CREST 0.15f
#define DEPTH 8           // ring slots (edges in flight per warp)

// ---------------- persistent device scratch --------------------------------
__device__ int  g_cnt[NMAX];      // zero at entry; scatter_k restores invariant
__device__ int  g_start[NMAX];    // exclusive row starts
__device__ int  g_cur[NMAX];      // scatter cursors (init = start)
__device__ int2 g_cv[2 * EMAX];   // packed {col | bit31 sign, val bits}
__device__ float g_PM[2][(size_t)2 * NMAX * DD];  // ping-pong, P then M

// ---------------- CSR build (3 launches) ------------------------------------
__global__ void hist_k(const int* __restrict__ rp, const int* __restrict__ rm, int E) {
    int i = blockIdx.x * blockDim.x + threadIdx.x;
    if (i < E) {
        atomicAdd(&g_cnt[rp[i]], 1);
        atomicAdd(&g_cnt[rm[i]], 1);
    }
}

__global__ void __launch_bounds__(1024)
scan_k(int n) {
    __shared__ int warp_inc[32];
    __shared__ int warp_off[32];
    __shared__ int red[32];
    __shared__ int sprefix;

    int tid  = threadIdx.x;
    int lane = tid & 31;
    int wid  = tid >> 5;
    int gid  = blockIdx.x * 1024 + tid;

    int v = (gid < n) ? g_cnt[gid] : 0;

    int x = v;
#pragma unroll
    for (int o = 1; o < 32; o <<= 1) {
        int y = __shfl_up_sync(0xffffffffu, x, o);
        if (lane >= o) x += y;
    }
    if (lane == 31) warp_inc[wid] = x;

    int ps = 0;
    int lim = blockIdx.x * 1024;
    for (int i = tid; i < lim; i += 1024) ps += g_cnt[i];
#pragma unroll
    for (int o = 16; o > 0; o >>= 1) ps += __shfl_down_sync(0xffffffffu, ps, o);
    if (lane == 0) red[wid] = ps;
    __syncthreads();

    if (tid < 32) {
        int s = warp_inc[tid];
        int t = s;
#pragma unroll
        for (int o = 1; o < 32; o <<= 1) {
            int y = __shfl_up_sync(0xffffffffu, t, o);
            if (tid >= o) t += y;
        }
        warp_off[tid] = t - s;
        int r = red[tid];
#pragma unroll
        for (int o = 16; o > 0; o >>= 1) r += __shfl_down_sync(0xffffffffu, r, o);
        if (tid == 0) sprefix = r;
    }
    __syncthreads();

    if (gid < n) {
        int st = sprefix + warp_off[wid] + (x - v);
        g_start[gid] = st;
        g_cur[gid]   = st;
    }
}

__global__ void scatter_k(const int* __restrict__ rp, const int* __restrict__ cp,
                          const float* __restrict__ vp,
                          const int* __restrict__ rm, const int* __restrict__ cm,
                          const float* __restrict__ vm, int E, int n) {
    int i = blockIdx.x * blockDim.x + threadIdx.x;
    if (i < n) g_cnt[i] = 0;   // restore invariant for next call
    if (i >= E) return;
    int pos = atomicAdd(&g_cur[rp[i]], 1);
    g_cv[pos] = make_int2(cp[i], __float_as_int(vp[i]));
    pos = atomicAdd(&g_cur[rm[i]], 1);
    g_cv[pos] = make_int2(cm[i] | 0x80000000, __float_as_int(vm[i]));
}

// ---------------- async-copy helper -----------------------------------------
__device__ __forceinline__ void cp16(unsigned saddr, const void* gptr) {
    asm volatile("cp.async.cg.shared.global [%0], [%1], 16;"
                 :: "r"(saddr), "l"(gptr));
}

// ---------------- fused diffusion iteration ---------------------------------
// One warp per row. Each edge's two 512B source rows are prefetched DEPTH
// edges ahead via cp.async.cg into a per-warp smem ring (lane-private 16B
// chunks -> no cross-lane sync; per-thread wait_group visibility suffices).
__global__ void __launch_bounds__(128)
diffuse_k(const float4* __restrict__ Ps, const float4* __restrict__ Ms,
          const float4* __restrict__ X4,
          float4* __restrict__ Pd, float4* __restrict__ Md,
          int n, int Etot) {
    __shared__ float4 ring[4][DEPTH][2][32];   // [warp][slot][A/B][lane] = 32KB

    int w = (blockIdx.x * blockDim.x + threadIdx.x) >> 5;
    int wb = threadIdx.x >> 5;
    unsigned lane = threadIdx.x & 31;
    if (w >= n) return;

    float4 x = __ldg(&X4[(unsigned)w * DV + lane]);
    float aP0 = CREST * x.x, aP1 = CREST * x.y, aP2 = CREST * x.z, aP3 = CREST * x.w;
    float aM0 = 0.f, aM1 = 0.f, aM2 = 0.f, aM3 = 0.f;

    int s = g_start[w];
    int e = (w + 1 < n) ? g_start[w + 1] : Etot;

    unsigned sbaseA = (unsigned)__cvta_generic_to_shared(&ring[wb][0][0][lane]);
    unsigned sbaseB = (unsigned)__cvta_generic_to_shared(&ring[wb][0][1][lane]);
    const unsigned slot_stride = 2 * 32 * sizeof(float4);   // bytes per slot

#define ISSUE(J, SLOT)                                                        \
    {                                                                         \
        int2 cv = __ldg(&g_cv[J]);                                            \
        int cj = cv.x;                                                        \
        unsigned off = (unsigned)(cj & 0x7fffffff) * DV + lane;               \
        const float4* A = (cj < 0) ? Ms : Ps;                                 \
        const float4* B = (cj < 0) ? Ps : Ms;                                 \
        cp16(sbaseA + (SLOT) * slot_stride, &A[off]);                         \
        cp16(sbaseB + (SLOT) * slot_stride, &B[off]);                         \
    }

    // prologue: fill up to DEPTH slots, committing one group per slot
#pragma unroll
    for (int k = 0; k < DEPTH; k++) {
        if (s + k < e) ISSUE(s + k, k);
        asm volatile("cp.async.commit_group;" ::: "memory");
    }

    // steady state: wait oldest group, consume, issue j+DEPTH, commit
    for (int j = s; j < e; j++) {
        asm volatile("cp.async.wait_group 7;" ::: "memory");
        int slot = (j - s) & (DEPTH - 1);
        float4 a = ring[wb][slot][0][lane];
        float4 b = ring[wb][slot][1][lane];
        int2 cv = __ldg(&g_cv[j]);                 // L1-hot broadcast (8B)
        float vj = __int_as_float(cv.y);
        aP0 += vj * a.x; aP1 += vj * a.y; aP2 += vj * a.z; aP3 += vj * a.w;
        aM0 += vj * b.x; aM1 += vj * b.y; aM2 += vj * b.z; aM3 += vj * b.w;
        int jn = j + DEPTH;
        if (jn < e) ISSUE(jn, slot);
        asm volatile("cp.async.commit_group;" ::: "memory");
    }
#undef ISSUE

    Pd[(unsigned)w * DV + lane] = make_float4(aP0, aP1, aP2, aP3);
    Md[(unsigned)w * DV + lane] = make_float4(aM0, aM1, aM2, aM3);
}

// ---------------- launch -----------------------------------------------------
extern "C" void kernel_launch(void* const* d_in, const int* in_sizes, int n_in,
                              void* d_out, int out_size) {
    const int*   rp = (const int*)d_in[0];
    const int*   cp = (const int*)d_in[1];
    const float* vp = (const float*)d_in[2];
    const int*   rm = (const int*)d_in[3];
    const int*   cm = (const int*)d_in[4];
    const float* vm = (const float*)d_in[5];
    const float* X  = (const float*)d_in[6];
    const float* M0 = (const float*)d_in[7];

    int E = in_sizes[0];
    int n = in_sizes[6] / DD;
    int Etot = 2 * E;

    hist_k<<<(E + 255) / 256, 256>>>(rp, rm, E);
    scan_k<<<(n + 1023) / 1024, 1024>>>(n);
    scatter_k<<<(E + 255) / 256, 256>>>(rp, cp, vp, rm, cm, vm, E, n);

    float* gPM = nullptr;
    cudaGetSymbolAddress((void**)&gPM, g_PM);

    const float* Ps = X;
    const float* Ms = M0;
    int grid = (n + 3) / 4;   // 4 warps / 128-thread block, 1 warp per row

    for (int it = 0; it < KITER; ++it) {
        float *Pd, *Md;
        if (it == KITER - 1) {
            Pd = (float*)d_out;
            Md = (float*)d_out + (size_t)n * DD;
        } else {
            int b = it & 1;
            float* basep = gPM + (size_t)b * 2 * NMAX * DD;
            Pd = basep;
            Md = basep + (size_t)n * DD;
        }
        diffuse_k<<<grid, 128>>>((const float4*)Ps, (const float4*)Ms,
                                 (const float4*)X, (float4*)Pd, (float4*)Md,
                                 n, Etot);
        Ps = Pd;
        Ms = Md;
    }
}

// round 14
// speedup vs baseline: 1.2164x; 1.2164x over previous
#include <cuda_runtime.h>

// SidNetLayer: N=50000, E=600000 per signed adjacency, D=128, K=10, C=0.15.
//   new_P = Ap*P + Am*M + 0.15*X
//   new_M = Am*P + Ap*M
// R14 (= R13 resubmit after infra transient): XOR-routed unified PM layout.
// P rows live at [0,N), M rows at [65536, 65536+N) inside ONE buffer.
// Scatter precomputes the accP source row (cA = c + neg*65536); the accM
// source row is always cA ^ 65536, i.e. offB = offA ^ (1<<21) in float4-
// offset space. This deletes the per-edge ISETP + 4xSEL pointer select of
// R7 — per-edge body: LDG.64 record, IMAD, LOP3, 2x LDG.128, 8 FFMA.

#define NMAX  50000
#define EMAX  600000
#define DD    128
#define DV    32                  // D/4 float4 per row
#define KITER 10
#define CREST 0.15f
#define MPART 65536               // M-partition start row (power of two > N)
#define ROWSPAN (MPART + NMAX)    // rows per buffer
#define XORF (MPART * DV)         // offset XOR mask in float4 units (1<<21)

// ---------------- persistent device scratch --------------------------------
__device__ int  g_cnt[NMAX];      // zero at entry; scatter_k restores invariant
__device__ int  g_start[NMAX];    // exclusive row starts
__device__ int  g_cur[NMAX];      // scatter cursors (init = start)
__device__ int2 g_cv[2 * EMAX];   // packed {cA row (sign folded in), val bits}
__device__ float g_PM[2][(size_t)ROWSPAN * DD];   // ping-pong unified buffers

// ---------------- CSR build (3 launches) ------------------------------------
__global__ void hist_k(const int* __restrict__ rp, const int* __restrict__ rm, int E) {
    int i = blockIdx.x * blockDim.x + threadIdx.x;
    if (i < E) {
        atomicAdd(&g_cnt[rp[i]], 1);
        atomicAdd(&g_cnt[rm[i]], 1);
    }
}

__global__ void __launch_bounds__(1024)
scan_k(int n) {
    __shared__ int warp_inc[32];
    __shared__ int warp_off[32];
    __shared__ int red[32];
    __shared__ int sprefix;

    int tid  = threadIdx.x;
    int lane = tid & 31;
    int wid  = tid >> 5;
    int gid  = blockIdx.x * 1024 + tid;

    int v = (gid < n) ? g_cnt[gid] : 0;

    int x = v;
#pragma unroll
    for (int o = 1; o < 32; o <<= 1) {
        int y = __shfl_up_sync(0xffffffffu, x, o);
        if (lane >= o) x += y;
    }
    if (lane == 31) warp_inc[wid] = x;

    int ps = 0;
    int lim = blockIdx.x * 1024;
    for (int i = tid; i < lim; i += 1024) ps += g_cnt[i];
#pragma unroll
    for (int o = 16; o > 0; o >>= 1) ps += __shfl_down_sync(0xffffffffu, ps, o);
    if (lane == 0) red[wid] = ps;
    __syncthreads();

    if (tid < 32) {
        int s = warp_inc[tid];
        int t = s;
#pragma unroll
        for (int o = 1; o < 32; o <<= 1) {
            int y = __shfl_up_sync(0xffffffffu, t, o);
            if (tid >= o) t += y;
        }
        warp_off[tid] = t - s;
        int r = red[tid];
#pragma unroll
        for (int o = 16; o > 0; o >>= 1) r += __shfl_down_sync(0xffffffffu, r, o);
        if (tid == 0) sprefix = r;
    }
    __syncthreads();

    if (gid < n) {
        int st = sprefix + warp_off[wid] + (x - v);
        g_start[gid] = st;
        g_cur[gid]   = st;
    }
}

__global__ void scatter_k(const int* __restrict__ rp, const int* __restrict__ cp,
                          const float* __restrict__ vp,
                          const int* __restrict__ rm, const int* __restrict__ cm,
                          const float* __restrict__ vm, int E, int n) {
    int i = blockIdx.x * blockDim.x + threadIdx.x;
    if (i < n) g_cnt[i] = 0;   // restore invariant for next call
    if (i >= E) return;
    // positive: accP reads P[c] -> cA = c (bit16 clear since c < 50000 < 65536)
    int pos = atomicAdd(&g_cur[rp[i]], 1);
    g_cv[pos] = make_int2(cp[i], __float_as_int(vp[i]));
    // negative: accP reads M[c] -> cA = c + MPART (bit16 set)
    pos = atomicAdd(&g_cur[rm[i]], 1);
    g_cv[pos] = make_int2(cm[i] + MPART, __float_as_int(vm[i]));
}

// ---------------- init copy: X, M0 -> unified PM layout ----------------------
__global__ void copy_in_k(const float4* __restrict__ X4,
                          const float4* __restrict__ M4,
                          float4* __restrict__ dst, int nv) {
    int i = blockIdx.x * blockDim.x + threadIdx.x;
    if (i < nv) {
        dst[i] = X4[i];
        dst[XORF + i] = M4[i];
    }
}

// ---------------- fused diffusion iteration ---------------------------------
// One warp per row, unified source buffer S.
//   accP += v * S[cA], accM += v * S[cA ^ MPART]   (offset XOR, one LOP3)
__global__ void __launch_bounds__(128)
diffuse_k(const float4* __restrict__ S,
          const float4* __restrict__ X4,
          float4* __restrict__ Pd, float4* __restrict__ Md,
          int n, int Etot) {
    int w = (blockIdx.x * blockDim.x + threadIdx.x) >> 5;
    unsigned lane = threadIdx.x & 31;
    if (w >= n) return;

    float4 x = __ldg(&X4[(unsigned)w * DV + lane]);
    float aP0 = CREST * x.x, aP1 = CREST * x.y, aP2 = CREST * x.z, aP3 = CREST * x.w;
    float aM0 = 0.f, aM1 = 0.f, aM2 = 0.f, aM3 = 0.f;

    int s = g_start[w];
    int e = (w + 1 < n) ? g_start[w + 1] : Etot;

#pragma unroll 4
    for (int j = s; j < e; j++) {
        // all lanes load the same 8B record: broadcast, 1 wavefront, L1-hot
        int2 cv = __ldg(&g_cv[j]);
        float vj = __int_as_float(cv.y);
        unsigned offA = (unsigned)cv.x * DV + lane;
        unsigned offB = offA ^ XORF;               // one LOP3, no selects
        float4 a = __ldg(&S[offA]);
        float4 b = __ldg(&S[offB]);
        aP0 += vj * a.x; aP1 += vj * a.y; aP2 += vj * a.z; aP3 += vj * a.w;
        aM0 += vj * b.x; aM1 += vj * b.y; aM2 += vj * b.z; aM3 += vj * b.w;
    }

    Pd[(unsigned)w * DV + lane] = make_float4(aP0, aP1, aP2, aP3);
    Md[(unsigned)w * DV + lane] = make_float4(aM0, aM1, aM2, aM3);
}

// ---------------- launch -----------------------------------------------------
extern "C" void kernel_launch(void* const* d_in, const int* in_sizes, int n_in,
                              void* d_out, int out_size) {
    const int*   rp = (const int*)d_in[0];
    const int*   cp = (const int*)d_in[1];
    const float* vp = (const float*)d_in[2];
    const int*   rm = (const int*)d_in[3];
    const int*   cm = (const int*)d_in[4];
    const float* vm = (const float*)d_in[5];
    const float* X  = (const float*)d_in[6];
    const float* M0 = (const float*)d_in[7];

    int E = in_sizes[0];
    int n = in_sizes[6] / DD;
    int Etot = 2 * E;
    int nv = n * DV;   // float4 count per dense matrix

    hist_k<<<(E + 255) / 256, 256>>>(rp, rm, E);
    scan_k<<<(n + 1023) / 1024, 1024>>>(n);
    scatter_k<<<(E + 255) / 256, 256>>>(rp, cp, vp, rm, cm, vm, E, n);

    float* gPM = nullptr;
    cudaGetSymbolAddress((void**)&gPM, g_PM);
    float* bufA = gPM;
    float* bufB = gPM + (size_t)ROWSPAN * DD;

    // stage X and M0 into the unified layout (buffer A)
    copy_in_k<<<(nv + 255) / 256, 256>>>((const float4*)X, (const float4*)M0,
                                         (float4*)bufA, nv);

    const float* src = bufA;
    int grid = (n + 3) / 4;   // 4 warps / 128-thread block, 1 warp per row

    for (int it = 0; it < KITER; ++it) {
        float *Pd, *Md, *nxt;
        if (it == KITER - 1) {
            Pd = (float*)d_out;
            Md = (float*)d_out + (size_t)n * DD;
            nxt = nullptr;
        } else {
            nxt = (src == bufA) ? bufB : bufA;
            Pd = nxt;                              // P rows at [0, N)
            Md = nxt + (size_t)MPART * DD;         // M rows at [MPART, MPART+N)
        }
        diffuse_k<<<grid, 128>>>((const float4*)src, (const float4*)X,
                                 (float4*)Pd, (float4*)Md, n, Etot);
        if (it < KITER - 1) src = nxt;
    }
}

// round 15
// speedup vs baseline: 1.2711x; 1.0450x over previous
#include <cuda_runtime.h>

// SidNetLayer: N=50000, E=600000 per signed adjacency, D=128, K=10, C=0.15.
//   new_P = Ap*P + Am*M + 0.15*X
//   new_M = Am*P + Ap*M
// R15 = R7 diffuse (best measured: merged signed CSR, sign in bit31, single
// loop with per-edge base-pointer select, broadcast LDG.64 records, float4
// gathers, 128-thread blocks, unroll 4) + vectorized CSR-build kernels.
// R8-R14 established that every structural deviation from this diffuse body
// (split loops, deeper unroll, explicit batching, dual rows, cp.async ring,
// XOR routing) measures worse; build kernels are the remaining headroom.

#define NMAX  50000
#define EMAX  600000
#define DD    128
#define DV    32          // D/4 float4 per row
#define KITER 10
#define CREST 0.15f

// ---------------- persistent device scratch --------------------------------
__device__ int  g_cnt[NMAX];      // zero at entry; scatter_k restores invariant
__device__ int  g_start[NMAX];    // exclusive row starts
__device__ int  g_cur[NMAX];      // scatter cursors (init = start)
__device__ int2 g_cv[2 * EMAX];   // packed {col | bit31 sign, val bits}
__device__ float g_PM[2][(size_t)2 * NMAX * DD];  // ping-pong, P then M

// ---------------- CSR build (3 launches) ------------------------------------
// 4 edges per thread via int4 loads (E % 4 == 0 for this problem; guarded).
__global__ void hist_k(const int* __restrict__ rp, const int* __restrict__ rm, int E) {
    int i = (blockIdx.x * blockDim.x + threadIdx.x) * 4;
    if (i + 4 <= E) {
        int4 a = *(const int4*)(rp + i);
        int4 b = *(const int4*)(rm + i);
        atomicAdd(&g_cnt[a.x], 1); atomicAdd(&g_cnt[a.y], 1);
        atomicAdd(&g_cnt[a.z], 1); atomicAdd(&g_cnt[a.w], 1);
        atomicAdd(&g_cnt[b.x], 1); atomicAdd(&g_cnt[b.y], 1);
        atomicAdd(&g_cnt[b.z], 1); atomicAdd(&g_cnt[b.w], 1);
    } else {
        for (; i < E; i++) {
            atomicAdd(&g_cnt[rp[i]], 1);
            atomicAdd(&g_cnt[rm[i]], 1);
        }
    }
}

__global__ void __launch_bounds__(1024)
scan_k(int n) {
    __shared__ int warp_inc[32];
    __shared__ int warp_off[32];
    __shared__ int red[32];
    __shared__ int sprefix;

    int tid  = threadIdx.x;
    int lane = tid & 31;
    int wid  = tid >> 5;
    int gid  = blockIdx.x * 1024 + tid;

    int v = (gid < n) ? g_cnt[gid] : 0;

    int x = v;
#pragma unroll
    for (int o = 1; o < 32; o <<= 1) {
        int y = __shfl_up_sync(0xffffffffu, x, o);
        if (lane >= o) x += y;
    }
    if (lane == 31) warp_inc[wid] = x;

    int ps = 0;
    int lim = blockIdx.x * 1024;
    for (int i = tid; i < lim; i += 1024) ps += g_cnt[i];
#pragma unroll
    for (int o = 16; o > 0; o >>= 1) ps += __shfl_down_sync(0xffffffffu, ps, o);
    if (lane == 0) red[wid] = ps;
    __syncthreads();

    if (tid < 32) {
        int s = warp_inc[tid];
        int t = s;
#pragma unroll
        for (int o = 1; o < 32; o <<= 1) {
            int y = __shfl_up_sync(0xffffffffu, t, o);
            if (tid >= o) t += y;
        }
        warp_off[tid] = t - s;
        int r = red[tid];
#pragma unroll
        for (int o = 16; o > 0; o >>= 1) r += __shfl_down_sync(0xffffffffu, r, o);
        if (tid == 0) sprefix = r;
    }
    __syncthreads();

    if (gid < n) {
        int st = sprefix + warp_off[wid] + (x - v);
        g_start[gid] = st;
        g_cur[gid]   = st;
    }
}

// 2 edges per thread via int2/float2 loads; atomic+store volume unchanged.
__global__ void scatter_k(const int* __restrict__ rp, const int* __restrict__ cp,
                          const float* __restrict__ vp,
                          const int* __restrict__ rm, const int* __restrict__ cm,
                          const float* __restrict__ vm, int E, int n) {
    int t = blockIdx.x * blockDim.x + threadIdx.x;
    if (t < n) g_cnt[t] = 0;   // restore invariant for next call
    int i = t * 2;
    if (i + 2 <= E) {
        int2   r0 = *(const int2*)(rp + i);
        int2   c0 = *(const int2*)(cp + i);
        float2 v0 = *(const float2*)(vp + i);
        int2   r1 = *(const int2*)(rm + i);
        int2   c1 = *(const int2*)(cm + i);
        float2 v1 = *(const float2*)(vm + i);
        int pos;
        pos = atomicAdd(&g_cur[r0.x], 1); g_cv[pos] = make_int2(c0.x, __float_as_int(v0.x));
        pos = atomicAdd(&g_cur[r0.y], 1); g_cv[pos] = make_int2(c0.y, __float_as_int(v0.y));
        pos = atomicAdd(&g_cur[r1.x], 1); g_cv[pos] = make_int2(c1.x | 0x80000000, __float_as_int(v1.x));
        pos = atomicAdd(&g_cur[r1.y], 1); g_cv[pos] = make_int2(c1.y | 0x80000000, __float_as_int(v1.y));
    } else {
        for (; i < E; i++) {
            int pos = atomicAdd(&g_cur[rp[i]], 1);
            g_cv[pos] = make_int2(cp[i], __float_as_int(vp[i]));
            pos = atomicAdd(&g_cur[rm[i]], 1);
            g_cv[pos] = make_int2(cm[i] | 0x80000000, __float_as_int(vm[i]));
        }
    }
}

// ---------------- fused diffusion iteration (exact R7 body) ------------------
// One warp per row. flag ? (accP += v*M[c], accM += v*P[c])
//                        : (accP += v*P[c], accM += v*M[c])
__global__ void __launch_bounds__(128)
diffuse_k(const float4* __restrict__ Ps, const float4* __restrict__ Ms,
          const float4* __restrict__ X4,
          float4* __restrict__ Pd, float4* __restrict__ Md,
          int n, int Etot) {
    int w = (blockIdx.x * blockDim.x + threadIdx.x) >> 5;
    unsigned lane = threadIdx.x & 31;
    if (w >= n) return;

    float4 x = __ldg(&X4[(unsigned)w * DV + lane]);
    float aP0 = CREST * x.x, aP1 = CREST * x.y, aP2 = CREST * x.z, aP3 = CREST * x.w;
    float aM0 = 0.f, aM1 = 0.f, aM2 = 0.f, aM3 = 0.f;

    int s = g_start[w];
    int e = (w + 1 < n) ? g_start[w + 1] : Etot;

#pragma unroll 4
    for (int j = s; j < e; j++) {
        // all lanes load the same 8B record: broadcast, 1 wavefront, L1-hot
        int2 cv = __ldg(&g_cv[j]);
        int   cj = cv.x;
        float vj = __int_as_float(cv.y);
        unsigned off = (unsigned)(cj & 0x7fffffff) * DV + lane;  // 32-bit math
        const float4* A = (cj < 0) ? Ms : Ps;   // feeds accP
        const float4* B = (cj < 0) ? Ps : Ms;   // feeds accM
        float4 a = __ldg(&A[off]);
        float4 b = __ldg(&B[off]);
        aP0 += vj * a.x; aP1 += vj * a.y; aP2 += vj * a.z; aP3 += vj * a.w;
        aM0 += vj * b.x; aM1 += vj * b.y; aM2 += vj * b.z; aM3 += vj * b.w;
    }

    Pd[(unsigned)w * DV + lane] = make_float4(aP0, aP1, aP2, aP3);
    Md[(unsigned)w * DV + lane] = make_float4(aM0, aM1, aM2, aM3);
}

// ---------------- launch -----------------------------------------------------
extern "C" void kernel_launch(void* const* d_in, const int* in_sizes, int n_in,
                              void* d_out, int out_size) {
    const int*   rp = (const int*)d_in[0];
    const int*   cp = (const int*)d_in[1];
    const float* vp = (const float*)d_in[2];
    const int*   rm = (const int*)d_in[3];
    const int*   cm = (const int*)d_in[4];
    const float* vm = (const float*)d_in[5];
    const float* X  = (const float*)d_in[6];
    const float* M0 = (const float*)d_in[7];

    int E = in_sizes[0];
    int n = in_sizes[6] / DD;
    int Etot = 2 * E;

    int histThreads = (E + 3) / 4;
    hist_k<<<(histThreads + 255) / 256, 256>>>(rp, rm, E);
    scan_k<<<(n + 1023) / 1024, 1024>>>(n);
    int scatThreads = (E + 1) / 2;
    int scatGridMin = (n + 255) / 256;                       // ensure g_cnt fully cleared
    int scatGrid = (scatThreads + 255) / 256;
    if (scatGrid < scatGridMin) scatGrid = scatGridMin;
    scatter_k<<<scatGrid, 256>>>(rp, cp, vp, rm, cm, vm, E, n);

    float* gPM = nullptr;
    cudaGetSymbolAddress((void**)&gPM, g_PM);

    const float* Ps = X;
    const float* Ms = M0;
    int grid = (n + 3) / 4;   // 4 warps / 128-thread block, 1 warp per row

    for (int it = 0; it < KITER; ++it) {
        float *Pd, *Md;
        if (it == KITER - 1) {
            Pd = (float*)d_out;
            Md = (float*)d_out + (size_t)n * DD;
        } else {
            int b = it & 1;
            float* basep = gPM + (size_t)b * 2 * NMAX * DD;
            Pd = basep;
            Md = basep + (size_t)n * DD;
        }
        diffuse_k<<<grid, 128>>>((const float4*)Ps, (const float4*)Ms,
                                 (const float4*)X, (float4*)Pd, (float4*)Md,
                                 n, Etot);
        Ps = Pd;
        Ms = Md;
    }
}